// round 2
// baseline (speedup 1.0000x reference)
#include <cuda_runtime.h>
#include <math.h>

#define FULLMASK 0xffffffffu
#define TPB 256
#define KMAX 32768

// ---------------- scratch (device globals; no allocation allowed) ----------
__device__ float g_cnt[KMAX];          // per-cluster cell count
__device__ float g_sum_sur[KMAX];      // sum of surprise
__device__ float g_sum_e[KMAX];        // sum of exp(w)
__device__ float g_sum_ea[KMAX * 4];   // sum of exp(w)*arch
__device__ float g_sum_a[KMAX * 4];    // sum of arch
__device__ float g_sum_sq[KMAX * 4];   // sum of arch^2
__device__ float g_impc[KMAX];         // per-cluster importance
__device__ int   g_spec[KMAX];         // per-cluster argmax(aggregate)

// ---------------- init ------------------------------------------------------
__global__ void init_kernel(int K) {
    int c = blockIdx.x * blockDim.x + threadIdx.x;
    if (c < K) {
        g_cnt[c] = 0.f; g_sum_sur[c] = 0.f; g_sum_e[c] = 0.f;
        #pragma unroll
        for (int a = 0; a < 4; a++) {
            g_sum_ea[c * 4 + a] = 0.f;
            g_sum_a [c * 4 + a] = 0.f;
            g_sum_sq[c * 4 + a] = 0.f;
        }
    }
}

// ---------------- pass A: per-cell MLP + segmented accumulation -------------
// w = clip(sigmoid(relu(feats@W1+b1)@W2+b2) * e*phi, .01, 1) * e*phi  (in [0,1))
// softmax is shift-invariant -> skip segment_max, accumulate exp(w) directly.
__global__ __launch_bounds__(TPB) void cell_kernel(
    const float* __restrict__ state, const float* __restrict__ arch,
    const float* __restrict__ energy, const float* __restrict__ phi,
    const float* __restrict__ sur, const int* __restrict__ seg,
    const float* __restrict__ W1, const float* __restrict__ b1,
    const float* __restrict__ W2, const float* __restrict__ b2,
    int N)
{
    __shared__ __align__(16) float W1s[36 * 64];
    __shared__ float b1s[64];
    __shared__ float W2s[64];
    __shared__ float b2s;
    for (int t = threadIdx.x; t < 36 * 64; t += TPB) W1s[t] = W1[t];
    if (threadIdx.x < 64) { b1s[threadIdx.x] = b1[threadIdx.x]; W2s[threadIdx.x] = W2[threadIdx.x]; }
    if (threadIdx.x == 0) b2s = b2[0];
    __syncthreads();

    int i    = blockIdx.x * TPB + threadIdx.x;
    int lane = threadIdx.x & 31;
    bool act = (i < N);

    float f[36];
    #pragma unroll
    for (int k = 0; k < 36; k++) f[k] = 0.f;
    float a4[4] = {0.f, 0.f, 0.f, 0.f};
    float aE = 0.f, aP = 0.f, aS = 0.f;
    int   sg = -1;

    if (act) {
        const float4* sp = reinterpret_cast<const float4*>(state + (size_t)i * 32);
        #pragma unroll
        for (int q = 0; q < 8; q++) {
            float4 v = sp[q];
            f[q * 4 + 0] = v.x; f[q * 4 + 1] = v.y; f[q * 4 + 2] = v.z; f[q * 4 + 3] = v.w;
        }
        float4 av = reinterpret_cast<const float4*>(arch)[i];
        f[32] = av.x; f[33] = av.y; f[34] = av.z; f[35] = av.w;
        a4[0] = av.x; a4[1] = av.y; a4[2] = av.z; a4[3] = av.w;
        aE = energy[i]; aP = phi[i]; aS = sur[i]; sg = seg[i];
    }

    // hidden layer in chunks of 8 to bound registers, fully unrolled FFMA core
    float s = b2s;
    #pragma unroll
    for (int jc = 0; jc < 64; jc += 8) {
        float acc[8];
        #pragma unroll
        for (int j = 0; j < 8; j++) acc[j] = b1s[jc + j];
        #pragma unroll
        for (int k = 0; k < 36; k++) {
            float fk = f[k];
            const float4* wp = reinterpret_cast<const float4*>(&W1s[k * 64 + jc]);
            float4 w0 = wp[0], w1 = wp[1];
            acc[0] = fmaf(fk, w0.x, acc[0]); acc[1] = fmaf(fk, w0.y, acc[1]);
            acc[2] = fmaf(fk, w0.z, acc[2]); acc[3] = fmaf(fk, w0.w, acc[3]);
            acc[4] = fmaf(fk, w1.x, acc[4]); acc[5] = fmaf(fk, w1.y, acc[5]);
            acc[6] = fmaf(fk, w1.z, acc[6]); acc[7] = fmaf(fk, w1.w, acc[7]);
        }
        #pragma unroll
        for (int j = 0; j < 8; j++) s = fmaf(fmaxf(acc[j], 0.f), W2s[jc + j], s);
    }

    float base = 1.f / (1.f + expf(-s));
    float ep   = aE * aP;
    float imp  = fminf(fmaxf(base * ep, 0.01f), 1.0f);
    float w    = imp * ep;               // in [0, 1)
    float e    = act ? expf(w) : 0.f;    // no shift needed, well-conditioned

    // 15 accumulands
    float vals[15];
    vals[0] = act ? 1.f : 0.f;           // count
    vals[1] = e;                          // sum exp
    vals[2] = e * a4[0]; vals[3] = e * a4[1]; vals[4] = e * a4[2]; vals[5] = e * a4[3];
    vals[6] = a4[0]; vals[7] = a4[1]; vals[8] = a4[2]; vals[9] = a4[3];
    vals[10] = a4[0] * a4[0]; vals[11] = a4[1] * a4[1];
    vals[12] = a4[2] * a4[2]; vals[13] = a4[3] * a4[3];
    vals[14] = aS;

    // segmented warp reduction (seg_ids sorted -> runs are contiguous)
    #pragma unroll
    for (int st = 0; st < 5; st++) {
        int off = 1 << st;
        int so  = __shfl_down_sync(FULLMASK, sg, off);
        bool ok = (lane + off < 32) && (so == sg);
        #pragma unroll
        for (int v = 0; v < 15; v++) {
            float t = __shfl_down_sync(FULLMASK, vals[v], off);
            if (ok) vals[v] += t;
        }
    }
    int  sprev = __shfl_up_sync(FULLMASK, sg, 1);
    bool head  = (lane == 0) || (sprev != sg);
    if (head && sg >= 0) {
        atomicAdd(&g_cnt[sg],     vals[0]);
        atomicAdd(&g_sum_e[sg],   vals[1]);
        atomicAdd(&g_sum_ea[sg * 4 + 0], vals[2]);
        atomicAdd(&g_sum_ea[sg * 4 + 1], vals[3]);
        atomicAdd(&g_sum_ea[sg * 4 + 2], vals[4]);
        atomicAdd(&g_sum_ea[sg * 4 + 3], vals[5]);
        atomicAdd(&g_sum_a [sg * 4 + 0], vals[6]);
        atomicAdd(&g_sum_a [sg * 4 + 1], vals[7]);
        atomicAdd(&g_sum_a [sg * 4 + 2], vals[8]);
        atomicAdd(&g_sum_a [sg * 4 + 3], vals[9]);
        atomicAdd(&g_sum_sq[sg * 4 + 0], vals[10]);
        atomicAdd(&g_sum_sq[sg * 4 + 1], vals[11]);
        atomicAdd(&g_sum_sq[sg * 4 + 2], vals[12]);
        atomicAdd(&g_sum_sq[sg * 4 + 3], vals[13]);
        atomicAdd(&g_sum_sur[sg], vals[14]);
    }
}

// ---------------- pass C: per-cluster math + small MLP + output rows --------
__global__ __launch_bounds__(256) void cluster_kernel(
    const float* __restrict__ V1, const float* __restrict__ c1,
    const float* __restrict__ V2, const float* __restrict__ c2,
    float* __restrict__ out, int K)
{
    __shared__ float V1s[7 * 32];
    __shared__ float c1s[32];
    __shared__ float V2s[32];
    __shared__ float c2s;
    for (int t = threadIdx.x; t < 7 * 32; t += 256) V1s[t] = V1[t];
    if (threadIdx.x < 32) { c1s[threadIdx.x] = c1[threadIdx.x]; V2s[threadIdx.x] = V2[threadIdx.x]; }
    if (threadIdx.x == 0) c2s = c2[0];
    __syncthreads();

    int c = blockIdx.x * blockDim.x + threadIdx.x;
    if (c >= K) return;

    float cnt   = g_cnt[c];
    bool  valid = cnt > 0.f;
    float inv_se = valid ? (1.f / g_sum_e[c]) : 0.f;

    // aggregate = softmax(sum(e*arch)/sum(e)); empty cluster -> softmax(0) = 0.25
    float agg[4], aggr[4];
    float mx = -1e30f;
    #pragma unroll
    for (int a = 0; a < 4; a++) { agg[a] = g_sum_ea[c * 4 + a] * inv_se; mx = fmaxf(mx, agg[a]); }
    float den = 0.f;
    #pragma unroll
    for (int a = 0; a < 4; a++) { aggr[a] = expf(agg[a] - mx); den += aggr[a]; }
    float invd = 1.f / den;
    #pragma unroll
    for (int a = 0; a < 4; a++) aggr[a] *= invd;

    // unbiased variance, same formula as reference
    float cnt1 = fmaxf(cnt, 1.f);
    float dvs  = 1.f / fmaxf(cnt - 1.f, 1.f);
    float vm = 0.f;
    #pragma unroll
    for (int a = 0; a < 4; a++) {
        float mean = g_sum_a[c * 4 + a] / cnt1;
        float var  = (g_sum_sq[c * 4 + a] - cnt * mean * mean) * dvs;
        vm += var;
    }
    vm *= 0.25f;
    float phi_c    = 1.f - fminf(1.f, vm * 2.f);
    float coh      = 1.f - vm;
    float pred_err = g_sum_sur[c] / cnt1;
    float integ    = phi_c * (1.f - pred_err);

    // cluster MLP: [7] -> relu[32] -> sigmoid scalar
    float cf[7] = { aggr[0], aggr[1], aggr[2], aggr[3], phi_c, coh, fminf(1.f, cnt * 0.05f) };
    float sc = c2s;
    #pragma unroll
    for (int j = 0; j < 32; j++) {
        float h = c1s[j];
        #pragma unroll
        for (int k = 0; k < 7; k++) h = fmaf(cf[k], V1s[k * 32 + j], h);
        sc = fmaf(fmaxf(h, 0.f), V2s[j], sc);
    }
    float basec = 1.f / (1.f + expf(-sc));
    float impc  = fminf(fmaxf(basec * phi_c, 0.01f), 1.f);
    g_impc[c] = impc;

    // argmax (first max wins, matching jnp.argmax)
    int sp = 0; float bv = aggr[0];
    #pragma unroll
    for (int a = 1; a < 4; a++) if (aggr[a] > bv) { bv = aggr[a]; sp = a; }
    g_spec[c] = sp;

    float* row = out + (size_t)c * 8;
    row[0] = aggr[0]; row[1] = aggr[1]; row[2] = aggr[2]; row[3] = aggr[3];
    row[4] = phi_c;   row[5] = coh;     row[6] = pred_err; row[7] = integ;
}

// ---------------- pass D: organism-level reduction (one block) --------------
__device__ __forceinline__ float blkReduceSum(float v, float* buf) {
    int t = threadIdx.x;
    buf[t] = v; __syncthreads();
    for (int s = 512; s; s >>= 1) { if (t < s) buf[t] += buf[t + s]; __syncthreads(); }
    float r = buf[0]; __syncthreads();
    return r;
}

__global__ __launch_bounds__(1024) void finalize_kernel(float* __restrict__ out, int K) {
    __shared__ float buf[1024];
    __shared__ int   ibuf[1024];
    int t = threadIdx.x;

    // phase 1: max impc over valid clusters
    float mx = -1e30f;
    for (int c = t; c < K; c += 1024)
        if (g_cnt[c] > 0.f) mx = fmaxf(mx, g_impc[c]);
    buf[t] = mx; __syncthreads();
    for (int s = 512; s; s >>= 1) { if (t < s) buf[t] = fmaxf(buf[t], buf[t + s]); __syncthreads(); }
    float M = buf[0]; __syncthreads();

    // phase 2: weighted sums over valid clusters
    float se = 0.f, sa0 = 0.f, sa1 = 0.f, sa2 = 0.f, sa3 = 0.f;
    float sphi = 0.f, scoh = 0.f, nval = 0.f;
    int   pres = 0;
    for (int c = t; c < K; c += 1024) {
        if (g_cnt[c] > 0.f) {
            float w = expf(g_impc[c] - M);
            const float* row = out + (size_t)c * 8;
            se += w;
            sa0 += w * row[0]; sa1 += w * row[1]; sa2 += w * row[2]; sa3 += w * row[3];
            sphi += row[4]; scoh += row[5]; nval += 1.f;
            pres |= (1 << g_spec[c]);
        }
    }
    se   = blkReduceSum(se,   buf);
    sa0  = blkReduceSum(sa0,  buf);
    sa1  = blkReduceSum(sa1,  buf);
    sa2  = blkReduceSum(sa2,  buf);
    sa3  = blkReduceSum(sa3,  buf);
    sphi = blkReduceSum(sphi, buf);
    scoh = blkReduceSum(scoh, buf);
    nval = blkReduceSum(nval, buf);
    ibuf[t] = pres; __syncthreads();
    for (int s = 512; s; s >>= 1) { if (t < s) ibuf[t] |= ibuf[t + s]; __syncthreads(); }
    pres = ibuf[0];

    if (t == 0) {
        float inv = 1.f / se;
        float g0 = sa0 * inv, g1 = sa1 * inv, g2 = sa2 * inv, g3 = sa3 * inv;
        float gm = fmaxf(fmaxf(g0, g1), fmaxf(g2, g3));
        float e0 = expf(g0 - gm), e1 = expf(g1 - gm), e2 = expf(g2 - gm), e3 = expf(g3 - gm);
        float gd = 1.f / (e0 + e1 + e2 + e3);
        float nv = fmaxf(nval, 1.f);
        float avg_phi = sphi / nv;
        float unique  = (float)__popc(pres & 0xF);
        float phi_global = fminf(1.f, avg_phi * (0.5f + 0.5f * unique * 0.25f));
        float vert = scoh / nv;
        float* sm = out + (size_t)K * 8;
        sm[0] = e0 * gd; sm[1] = e1 * gd; sm[2] = e2 * gd; sm[3] = e3 * gd;
        sm[4] = phi_global; sm[5] = vert;
    }
}

// ---------------- launch ----------------------------------------------------
extern "C" void kernel_launch(void* const* d_in, const int* in_sizes, int n_in,
                              void* d_out, int out_size)
{
    const float* state  = (const float*)d_in[0];
    const float* arch   = (const float*)d_in[1];
    const float* energy = (const float*)d_in[2];
    const float* phi    = (const float*)d_in[3];
    const float* sur    = (const float*)d_in[4];
    const int*   seg    = (const int*)  d_in[5];
    // d_in[6] = n_clusters (unused; derived from out_size)
    const float* W1 = (const float*)d_in[7];
    const float* b1 = (const float*)d_in[8];
    const float* W2 = (const float*)d_in[9];
    const float* b2 = (const float*)d_in[10];
    const float* V1 = (const float*)d_in[11];
    const float* c1 = (const float*)d_in[12];
    const float* V2 = (const float*)d_in[13];
    const float* c2 = (const float*)d_in[14];

    int N = in_sizes[2];                 // energy has N elements
    int K = (out_size - 6) / 8;          // K*8 cluster rows + 6-float self model
    if (K > KMAX) K = KMAX;              // scratch bound (K=16384 in practice)
    float* out = (float*)d_out;

    init_kernel<<<(K + 255) / 256, 256>>>(K);
    cell_kernel<<<(N + TPB - 1) / TPB, TPB>>>(state, arch, energy, phi, sur, seg,
                                              W1, b1, W2, b2, N);
    cluster_kernel<<<(K + 255) / 256, 256>>>(V1, c1, V2, c2, out, K);
    finalize_kernel<<<1, 1024>>>(out, K);
}

// round 5
// speedup vs baseline: 1.3530x; 1.3530x over previous
#include <cuda_runtime.h>
#include <math.h>

#define FULLMASK 0xffffffffu
#define KMAX 32768

typedef unsigned long long u64;

__device__ __forceinline__ void ffma2(u64 &d, u64 a, u64 b) {
    asm("fma.rn.f32x2 %0, %1, %2, %0;" : "+l"(d) : "l"(a), "l"(b));
}
__device__ __forceinline__ u64 pack2(float lo, float hi) {
    u64 r; asm("mov.b64 %0, {%1, %2};" : "=l"(r) : "f"(lo), "f"(hi)); return r;
}
__device__ __forceinline__ void unpack2(u64 v, float &lo, float &hi) {
    asm("mov.b64 {%0, %1}, %2;" : "=f"(lo), "=f"(hi) : "l"(v));
}

// ---------------- scratch (device globals; no allocation allowed) ----------
__device__ float g_cnt[KMAX];          // per-cluster cell count
__device__ float g_sum_sur[KMAX];      // sum of surprise
__device__ float g_sum_e[KMAX];        // sum of exp(w)
__device__ float g_sum_ea[KMAX * 4];   // sum of exp(w)*arch
__device__ float g_sum_a[KMAX * 4];    // sum of arch
__device__ float g_sum_sq[KMAX * 4];   // sum of arch^2
__device__ float g_final[8];           // se, sa0..3, sphi, scoh, nval
__device__ int   g_pres;               // presence bitmask of specializations

// ---------------- init ------------------------------------------------------
__global__ void init_kernel(int K) {
    int c = blockIdx.x * blockDim.x + threadIdx.x;
    if (c < K) {
        g_cnt[c] = 0.f; g_sum_sur[c] = 0.f; g_sum_e[c] = 0.f;
        #pragma unroll
        for (int a = 0; a < 4; a++) {
            g_sum_ea[c * 4 + a] = 0.f;
            g_sum_a [c * 4 + a] = 0.f;
            g_sum_sq[c * 4 + a] = 0.f;
        }
    }
    if (blockIdx.x == 0 && threadIdx.x < 8) g_final[threadIdx.x] = 0.f;
    if (blockIdx.x == 0 && threadIdx.x == 0) g_pres = 0;
}

// ---------------- pass A: per-cell MLP + segmented accumulation -------------
// Lane l owns hidden units (2l, 2l+1); W1 register-resident packed over
// k-pairs. Features staged in smem rows of 36 floats; LDS.64 broadcast gives
// a ready-packed (f[2t], f[2t+1]) operand for fma.rn.f32x2.
#define ROW_F 36
__global__ __launch_bounds__(128, 4) void cell_kernel(
    const float* __restrict__ state, const float* __restrict__ arch,
    const float* __restrict__ energy, const float* __restrict__ phi,
    const float* __restrict__ sur, const int* __restrict__ seg,
    const float* __restrict__ W1, const float* __restrict__ b1,
    const float* __restrict__ W2, const float* __restrict__ b2,
    int N)
{
    __shared__ __align__(16) float feat[128 * ROW_F];   // 18 KB
    const int tid  = threadIdx.x;
    const int lane = tid & 31;
    const int warp = tid >> 5;

    // one-time: register the weights for this lane's two hidden units
    u64 w0[18], w1[18];
    #pragma unroll
    for (int t = 0; t < 18; t++) {
        w0[t] = pack2(W1[(2 * t) * 64 + 2 * lane],     W1[(2 * t + 1) * 64 + 2 * lane]);
        w1[t] = pack2(W1[(2 * t) * 64 + 2 * lane + 1], W1[(2 * t + 1) * 64 + 2 * lane + 1]);
    }
    const u64 b1p0 = pack2(b1[2 * lane], 0.f);
    const u64 b1p1 = pack2(b1[2 * lane + 1], 0.f);
    const float w2a = W2[2 * lane], w2b = W2[2 * lane + 1];
    const float b2v = b2[0];

    const int stride = gridDim.x * 128;
    for (int base = blockIdx.x * 128; base < N; base += stride) {
        __syncthreads();                    // previous chunk's reads done
        // stage 128 cells: state (32f) + arch (4f) -> rows of 36 floats
        #pragma unroll
        for (int r = 0; r < 8; r++) {
            int idx  = tid + r * 128;
            int c    = idx >> 3, q = idx & 7;
            int cell = min(base + c, N - 1);
            float4 v = reinterpret_cast<const float4*>(state)[(size_t)cell * 8 + q];
            *reinterpret_cast<float4*>(&feat[c * ROW_F + q * 4]) = v;
        }
        {
            int cell = min(base + tid, N - 1);
            float4 v = reinterpret_cast<const float4*>(arch)[cell];
            *reinterpret_cast<float4*>(&feat[tid * ROW_F + 32]) = v;
        }
        // per-lane scalars (issue early, hide latency under compute)
        int  myCell = base + warp * 32 + lane;
        bool act    = myCell < N;
        int  safeC  = act ? myCell : 0;
        float aE = act ? energy[safeC] : 0.f;
        float aP = act ? phi[safeC]    : 0.f;
        float aS = act ? sur[safeC]    : 0.f;
        int   sg = act ? seg[safeC]    : -1;
        __syncthreads();

        // compute the 32 cells of this warp; lane c keeps cell c's logit
        float s_keep = 0.f;
        const int rowBase = warp * 32 * ROW_F;
        #pragma unroll 2
        for (int c = 0; c < 32; c++) {
            const u64* fp = reinterpret_cast<const u64*>(&feat[rowBase + c * ROW_F]);
            u64 acc0 = b1p0, acc1 = b1p1;
            #pragma unroll
            for (int t = 0; t < 18; t++) {
                u64 f2 = fp[t];                 // LDS.64 broadcast
                ffma2(acc0, f2, w0[t]);
                ffma2(acc1, f2, w1[t]);
            }
            float x0, x1, y0, y1;
            unpack2(acc0, x0, x1); unpack2(acc1, y0, y1);
            float h0 = fmaxf(x0 + x1, 0.f), h1 = fmaxf(y0 + y1, 0.f);
            float sp = fmaf(h0, w2a, h1 * w2b);
            #pragma unroll
            for (int o = 16; o; o >>= 1) sp += __shfl_xor_sync(FULLMASK, sp, o);
            if (lane == c) s_keep = sp + b2v;
        }

        // per-lane epilogue for its own cell
        const float* ar = &feat[(warp * 32 + lane) * ROW_F + 32];
        float a0 = ar[0], a1 = ar[1], a2 = ar[2], a3 = ar[3];

        float bse = 1.f / (1.f + expf(-s_keep));
        float ep  = aE * aP;
        float imp = fminf(fmaxf(bse * ep, 0.01f), 1.0f);
        float w   = imp * ep;                 // in [0,1)
        float e   = act ? expf(w) : 0.f;      // softmax shift-invariant: no max pass

        float vals[15];
        vals[0]  = act ? 1.f : 0.f;
        vals[1]  = e;
        vals[2]  = e * a0; vals[3] = e * a1; vals[4] = e * a2; vals[5] = e * a3;
        vals[6]  = act ? a0 : 0.f; vals[7]  = act ? a1 : 0.f;
        vals[8]  = act ? a2 : 0.f; vals[9]  = act ? a3 : 0.f;
        vals[10] = act ? a0 * a0 : 0.f; vals[11] = act ? a1 * a1 : 0.f;
        vals[12] = act ? a2 * a2 : 0.f; vals[13] = act ? a3 * a3 : 0.f;
        vals[14] = act ? aS : 0.f;

        // segmented warp reduction (seg_ids sorted -> runs contiguous)
        #pragma unroll
        for (int st = 0; st < 5; st++) {
            int off = 1 << st;
            int so  = __shfl_down_sync(FULLMASK, sg, off);
            bool ok = (lane + off < 32) && (so == sg);
            #pragma unroll
            for (int v = 0; v < 15; v++) {
                float t = __shfl_down_sync(FULLMASK, vals[v], off);
                if (ok) vals[v] += t;
            }
        }
        int  sprev = __shfl_up_sync(FULLMASK, sg, 1);
        bool head  = (lane == 0) || (sprev != sg);
        if (head && sg >= 0) {
            atomicAdd(&g_cnt[sg],     vals[0]);
            atomicAdd(&g_sum_e[sg],   vals[1]);
            atomicAdd(&g_sum_ea[sg * 4 + 0], vals[2]);
            atomicAdd(&g_sum_ea[sg * 4 + 1], vals[3]);
            atomicAdd(&g_sum_ea[sg * 4 + 2], vals[4]);
            atomicAdd(&g_sum_ea[sg * 4 + 3], vals[5]);
            atomicAdd(&g_sum_a [sg * 4 + 0], vals[6]);
            atomicAdd(&g_sum_a [sg * 4 + 1], vals[7]);
            atomicAdd(&g_sum_a [sg * 4 + 2], vals[8]);
            atomicAdd(&g_sum_a [sg * 4 + 3], vals[9]);
            atomicAdd(&g_sum_sq[sg * 4 + 0], vals[10]);
            atomicAdd(&g_sum_sq[sg * 4 + 1], vals[11]);
            atomicAdd(&g_sum_sq[sg * 4 + 2], vals[12]);
            atomicAdd(&g_sum_sq[sg * 4 + 3], vals[13]);
            atomicAdd(&g_sum_sur[sg], vals[14]);
        }
    }
}

// ---------------- pass C: cluster math + MLP + fused organism reduction ----
// impc in [0.01, 1] -> softmax over impc needs NO max pass: accumulate
// exp(impc) and exp(impc)*aggregate directly with atomics.
__global__ __launch_bounds__(256) void cluster_kernel(
    const float* __restrict__ V1, const float* __restrict__ c1,
    const float* __restrict__ V2, const float* __restrict__ c2,
    float* __restrict__ out, int K)
{
    __shared__ float V1s[7 * 32];
    __shared__ float c1s[32];
    __shared__ float V2s[32];
    __shared__ float c2s;
    for (int t = threadIdx.x; t < 7 * 32; t += 256) V1s[t] = V1[t];
    if (threadIdx.x < 32) { c1s[threadIdx.x] = c1[threadIdx.x]; V2s[threadIdx.x] = V2[threadIdx.x]; }
    if (threadIdx.x == 0) c2s = c2[0];
    __syncthreads();

    int c    = blockIdx.x * blockDim.x + threadIdx.x;
    int lane = threadIdx.x & 31;
    bool inb = c < K;

    float contrib[8] = {0.f, 0.f, 0.f, 0.f, 0.f, 0.f, 0.f, 0.f};
    int   presb = 0;

    if (inb) {
        float cnt   = g_cnt[c];
        bool  valid = cnt > 0.f;
        float inv_se = valid ? (1.f / g_sum_e[c]) : 0.f;

        float agg[4], aggr[4];
        float mx = -1e30f;
        #pragma unroll
        for (int a = 0; a < 4; a++) { agg[a] = g_sum_ea[c * 4 + a] * inv_se; mx = fmaxf(mx, agg[a]); }
        float den = 0.f;
        #pragma unroll
        for (int a = 0; a < 4; a++) { aggr[a] = expf(agg[a] - mx); den += aggr[a]; }
        float invd = 1.f / den;
        #pragma unroll
        for (int a = 0; a < 4; a++) aggr[a] *= invd;

        float cnt1 = fmaxf(cnt, 1.f);
        float dvs  = 1.f / fmaxf(cnt - 1.f, 1.f);
        float vm = 0.f;
        #pragma unroll
        for (int a = 0; a < 4; a++) {
            float mean = g_sum_a[c * 4 + a] / cnt1;
            float var  = (g_sum_sq[c * 4 + a] - cnt * mean * mean) * dvs;
            vm += var;
        }
        vm *= 0.25f;
        float phi_c    = 1.f - fminf(1.f, vm * 2.f);
        float coh      = 1.f - vm;
        float pred_err = g_sum_sur[c] / cnt1;
        float integ    = phi_c * (1.f - pred_err);

        float cf[7] = { aggr[0], aggr[1], aggr[2], aggr[3], phi_c, coh, fminf(1.f, cnt * 0.05f) };
        float sc = c2s;
        #pragma unroll
        for (int j = 0; j < 32; j++) {
            float h = c1s[j];
            #pragma unroll
            for (int k = 0; k < 7; k++) h = fmaf(cf[k], V1s[k * 32 + j], h);
            sc = fmaf(fmaxf(h, 0.f), V2s[j], sc);
        }
        float basec = 1.f / (1.f + expf(-sc));
        float impc  = fminf(fmaxf(basec * phi_c, 0.01f), 1.f);

        int sp = 0; float bv = aggr[0];
        #pragma unroll
        for (int a = 1; a < 4; a++) if (aggr[a] > bv) { bv = aggr[a]; sp = a; }

        float* row = out + (size_t)c * 8;
        row[0] = aggr[0]; row[1] = aggr[1]; row[2] = aggr[2]; row[3] = aggr[3];
        row[4] = phi_c;   row[5] = coh;     row[6] = pred_err; row[7] = integ;

        if (valid) {
            float ew = expf(impc);
            contrib[0] = ew;
            contrib[1] = ew * aggr[0]; contrib[2] = ew * aggr[1];
            contrib[3] = ew * aggr[2]; contrib[4] = ew * aggr[3];
            contrib[5] = phi_c; contrib[6] = coh; contrib[7] = 1.f;
            presb = 1 << sp;
        }
    }

    // warp reduce + one atomic set per warp
    #pragma unroll
    for (int o = 16; o; o >>= 1) {
        #pragma unroll
        for (int v = 0; v < 8; v++) contrib[v] += __shfl_xor_sync(FULLMASK, contrib[v], o);
        presb |= __shfl_xor_sync(FULLMASK, presb, o);
    }
    if (lane == 0) {
        #pragma unroll
        for (int v = 0; v < 8; v++) atomicAdd(&g_final[v], contrib[v]);
        atomicOr(&g_pres, presb);
    }
}

// ---------------- pass D: trivial organism finalize -------------------------
__global__ void finalize_kernel(float* __restrict__ out, int K) {
    if (threadIdx.x != 0) return;
    float se  = g_final[0];
    float inv = 1.f / se;
    float g0 = g_final[1] * inv, g1 = g_final[2] * inv;
    float g2 = g_final[3] * inv, g3 = g_final[4] * inv;
    float gm = fmaxf(fmaxf(g0, g1), fmaxf(g2, g3));
    float e0 = expf(g0 - gm), e1 = expf(g1 - gm), e2 = expf(g2 - gm), e3 = expf(g3 - gm);
    float gd = 1.f / (e0 + e1 + e2 + e3);
    float nv = fmaxf(g_final[7], 1.f);
    float avg_phi = g_final[5] / nv;
    float unique  = (float)__popc(g_pres & 0xF);
    float phi_global = fminf(1.f, avg_phi * (0.5f + 0.5f * unique * 0.25f));
    float vert = g_final[6] / nv;
    float* sm = out + (size_t)K * 8;
    sm[0] = e0 * gd; sm[1] = e1 * gd; sm[2] = e2 * gd; sm[3] = e3 * gd;
    sm[4] = phi_global; sm[5] = vert;
}

// ---------------- launch ----------------------------------------------------
extern "C" void kernel_launch(void* const* d_in, const int* in_sizes, int n_in,
                              void* d_out, int out_size)
{
    const float* state  = (const float*)d_in[0];
    const float* arch   = (const float*)d_in[1];
    const float* energy = (const float*)d_in[2];
    const float* phi    = (const float*)d_in[3];
    const float* sur    = (const float*)d_in[4];
    const int*   seg    = (const int*)  d_in[5];
    const float* W1 = (const float*)d_in[7];
    const float* b1 = (const float*)d_in[8];
    const float* W2 = (const float*)d_in[9];
    const float* b2 = (const float*)d_in[10];
    const float* V1 = (const float*)d_in[11];
    const float* c1 = (const float*)d_in[12];
    const float* V2 = (const float*)d_in[13];
    const float* c2 = (const float*)d_in[14];

    int N = in_sizes[2];                 // energy has N elements
    int K = (out_size - 6) / 8;
    if (K > KMAX) K = KMAX;
    float* out = (float*)d_out;

    int chunks = (N + 127) / 128;
    int blocks = chunks < 592 ? chunks : 592;   // 4 blocks/SM persistent wave

    init_kernel<<<(K + 255) / 256, 256>>>(K);
    cell_kernel<<<blocks, 128>>>(state, arch, energy, phi, sur, seg,
                                 W1, b1, W2, b2, N);
    cluster_kernel<<<(K + 255) / 256, 256>>>(V1, c1, V2, c2, out, K);
    finalize_kernel<<<1, 32>>>(out, K);
}